// round 1
// baseline (speedup 1.0000x reference)
#include <cuda_runtime.h>

#define NN 50000
#define EE 800000
#define ETOT (EE + NN)

// ---------------- scratch (__device__ globals: no allocation allowed) ----------------
__device__ float  g_xh_cov[(size_t)NN * 1024];   // [N, H=4, 256] folded projection
__device__ float  g_xh_mean[(size_t)NN * 64];    // [N, 4, 16]
__device__ float4 g_asrc_cov[NN], g_adst_cov[NN];
__device__ float4 g_asrc_mean[NN], g_adst_mean[NN];
__device__ float  g_Wc2[256 * 256];              // fcv_W1 @ fcv_W2
__device__ float  g_Wfold_cov[256 * 1024];       // per-head W_h @ Wc2
__device__ float  g_Wfold_mean[16 * 64];
__device__ float4 g_wsrc_cov[256], g_wdst_cov[256];   // [r][h] folded attention vecs
__device__ float4 g_wsrc_mean[16], g_wdst_mean[16];
__device__ float  g_bias_cov_out[256];
__device__ float  g_bias_mean_out[16];
__device__ int    g_counts[NN];
__device__ int    g_offsets[NN + 1];
__device__ int    g_cursor[NN];
__device__ int    g_csr_src[ETOT];
__device__ float4 g_alpha_cov[ETOT];
__device__ float4 g_alpha_mean[ETOT];

__device__ __forceinline__ float lrelu(float x) { return x > 0.f ? x : 0.2f * x; }

__device__ __forceinline__ void wred_max4(float4& v) {
#pragma unroll
    for (int o = 16; o; o >>= 1) {
        v.x = fmaxf(v.x, __shfl_xor_sync(0xffffffffu, v.x, o));
        v.y = fmaxf(v.y, __shfl_xor_sync(0xffffffffu, v.y, o));
        v.z = fmaxf(v.z, __shfl_xor_sync(0xffffffffu, v.z, o));
        v.w = fmaxf(v.w, __shfl_xor_sync(0xffffffffu, v.w, o));
    }
}
__device__ __forceinline__ void wred_sum4(float4& v) {
#pragma unroll
    for (int o = 16; o; o >>= 1) {
        v.x += __shfl_xor_sync(0xffffffffu, v.x, o);
        v.y += __shfl_xor_sync(0xffffffffu, v.y, o);
        v.z += __shfl_xor_sync(0xffffffffu, v.z, o);
        v.w += __shfl_xor_sync(0xffffffffu, v.w, o);
    }
}

// ---------------- tiny precompute kernels ----------------

// Wm2 = fm_W1 @ fm_W2 ; bias_mean_out ; mean attention folds ; Wfold_mean
__global__ void k_prep_mean(const float* __restrict__ fmW1, const float* __restrict__ fmW2,
                            const float* __restrict__ fmb1, const float* __restrict__ fmb2,
                            const float* __restrict__ bias_mean, const float* __restrict__ W_mean,
                            const float* __restrict__ att_src, const float* __restrict__ att_dst) {
    __shared__ float Wm2s[16][16];
    int t = threadIdx.x;
    {
        int r = t >> 4, c = t & 15;
        float s = 0.f;
        for (int k = 0; k < 16; k++) s += fmW1[r * 16 + k] * fmW2[k * 16 + c];
        Wm2s[r][c] = s;
    }
    // attention folds (independent of Wm2)
    if (t < 128) {
        int sd = t >> 6, rem = t & 63, r = rem >> 2, h = rem & 3;
        const float* att = sd ? att_dst : att_src;
        float s = 0.f;
        for (int j = 0; j < 16; j++) s += W_mean[r * 64 + h * 16 + j] * att[h * 16 + j];
        float* dstp = sd ? (float*)g_wdst_mean : (float*)g_wsrc_mean;
        dstp[r * 4 + h] = s;
    }
    __syncthreads();
    if (t < 16) {
        float b = fmb2[t];
        for (int k = 0; k < 16; k++)
            b += bias_mean[k] * Wm2s[k][t] + fmb1[k] * fmW2[k * 16 + t];
        g_bias_mean_out[t] = b;
    }
    for (int o = t; o < 1024; o += 256) {
        int r = o >> 6, hc = o & 63, h = hc >> 4, c = hc & 15;
        float s = 0.f;
        for (int j = 0; j < 16; j++) s += W_mean[r * 64 + h * 16 + j] * Wm2s[j][c];
        g_Wfold_mean[o] = s;
    }
}

// Wc2 = fcv_W1 @ fcv_W2  (grid 256 x 256 threads)
__global__ void k_Wc2(const float* __restrict__ W1, const float* __restrict__ W2) {
    int r = blockIdx.x, c = threadIdx.x;
    float s = 0.f;
    for (int k = 0; k < 256; k++) s += W1[r * 256 + k] * W2[k * 256 + c];
    g_Wc2[r * 256 + c] = s;
}

// bias_cov_out = bias_cov@Wc2 + fcv_b1@fcv_W2 + fcv_b2
__global__ void k_bias_cov(const float* __restrict__ bias_cov, const float* __restrict__ fb1,
                           const float* __restrict__ fW2, const float* __restrict__ fb2) {
    int c = threadIdx.x;
    float b = fb2[c];
    for (int k = 0; k < 256; k++)
        b += bias_cov[k] * g_Wc2[k * 256 + c] + fb1[k] * fW2[k * 256 + c];
    g_bias_cov_out[c] = b;
}

// Wfold_cov[r][h*256+c] = sum_j W_cov[r][h*256+j] * Wc2[j][c]   (grid 1024)
__global__ void k_Wfold_cov(const float* __restrict__ W_cov) {
    int bid = blockIdx.x;
    int r = bid >> 2, seg = bid & 3, t = threadIdx.x;
    const float* wrow = W_cov + (size_t)r * 1024 + seg * 256;
    float s = 0.f;
    for (int j = 0; j < 256; j++) s += wrow[j] * g_Wc2[j * 256 + t];
    g_Wfold_cov[(size_t)r * 1024 + seg * 256 + t] = s;
}

// cov attention folds: wsrc/wdst_cov[r][h] = sum_j W_cov[r][h*256+j]*att[h][j]  (grid 8)
__global__ void k_att_cov(const float* __restrict__ W_cov, const float* __restrict__ att_src,
                          const float* __restrict__ att_dst) {
    int o = blockIdx.x * 256 + threadIdx.x;     // 0..2047
    int sd = o >> 10, rem = o & 1023, r = rem >> 2, h = rem & 3;
    const float* att = sd ? att_dst : att_src;
    const float* wrow = W_cov + (size_t)r * 1024 + h * 256;
    float s = 0.f;
    for (int j = 0; j < 256; j++) s += wrow[j] * att[h * 256 + j];
    float* dstp = sd ? (float*)g_wdst_cov : (float*)g_wsrc_cov;
    dstp[r * 4 + h] = s;
}

// per-node attention logits a_src/a_dst (cov + mean), warp per node
__global__ void k_a(const float* __restrict__ mean, const float* __restrict__ cov) {
    int warp = threadIdx.x >> 5, lane = threadIdx.x & 31;
    int n = blockIdx.x * 8 + warp;
    if (n >= NN) return;
    const float* x = cov + (size_t)n * 256;
    float4 as = make_float4(0, 0, 0, 0), ad = make_float4(0, 0, 0, 0);
    for (int r = lane; r < 256; r += 32) {
        float xv = __ldg(x + r);
        float4 ws = g_wsrc_cov[r], wd = g_wdst_cov[r];
        as.x += xv * ws.x; as.y += xv * ws.y; as.z += xv * ws.z; as.w += xv * ws.w;
        ad.x += xv * wd.x; ad.y += xv * wd.y; ad.z += xv * wd.z; ad.w += xv * wd.w;
    }
    wred_sum4(as); wred_sum4(ad);
    float4 ms = make_float4(0, 0, 0, 0), md = make_float4(0, 0, 0, 0);
    if (lane < 16) {
        float xv = __ldg(mean + (size_t)n * 16 + lane);
        float4 ws = g_wsrc_mean[lane], wd = g_wdst_mean[lane];
        ms = make_float4(xv * ws.x, xv * ws.y, xv * ws.z, xv * ws.w);
        md = make_float4(xv * wd.x, xv * wd.y, xv * wd.z, xv * wd.w);
    }
    wred_sum4(ms); wred_sum4(md);
    if (lane == 0) {
        g_asrc_cov[n] = as; g_adst_cov[n] = ad;
        g_asrc_mean[n] = ms; g_adst_mean[n] = md;
    }
}

// ---------------- CSR build ----------------
__global__ void k_init_counts() {
    int i = blockIdx.x * 256 + threadIdx.x;
    if (i < NN) g_counts[i] = 1;   // self loop
}
__global__ void k_hist(const int* __restrict__ ei) {
    int e = blockIdx.x * 256 + threadIdx.x;
    if (e < EE) atomicAdd(&g_counts[ei[EE + e]], 1);
}
__global__ void k_scan() {   // single block, 1024 threads
    __shared__ int ssum[1024];
    int t = threadIdx.x;
    const int PER = (NN + 1023) / 1024;
    int base = t * PER;
    int local = 0;
    for (int i = 0; i < PER; i++) { int idx = base + i; if (idx < NN) local += g_counts[idx]; }
    ssum[t] = local;
    __syncthreads();
    for (int off = 1; off < 1024; off <<= 1) {
        int v = (t >= off) ? ssum[t - off] : 0;
        __syncthreads();
        ssum[t] += v;
        __syncthreads();
    }
    int prefix = (t == 0) ? 0 : ssum[t - 1];
    for (int i = 0; i < PER; i++) {
        int idx = base + i;
        if (idx < NN) {
            g_offsets[idx] = prefix;
            g_cursor[idx] = prefix;
            prefix += g_counts[idx];
        }
    }
    if (t == 1023) g_offsets[NN] = ssum[1023];
}
__global__ void k_scatter(const int* __restrict__ ei) {
    int e = blockIdx.x * 256 + threadIdx.x;
    if (e >= ETOT) return;
    int s, d;
    if (e < EE) { s = ei[e]; d = ei[EE + e]; }
    else        { s = e - EE; d = s; }
    int pos = atomicAdd(&g_cursor[d], 1);
    g_csr_src[pos] = s;
    float4 a = g_asrc_cov[s], b = g_adst_cov[d];
    g_alpha_cov[pos] = make_float4(lrelu(a.x + b.x), lrelu(a.y + b.y),
                                   lrelu(a.z + b.z), lrelu(a.w + b.w));
    a = g_asrc_mean[s]; b = g_adst_mean[d];
    g_alpha_mean[pos] = make_float4(lrelu(a.x + b.x), lrelu(a.y + b.y),
                                    lrelu(a.z + b.z), lrelu(a.w + b.w));
}

// ---------------- GEMMs ----------------
// xh_cov = cov[50000,256] @ Wfold_cov[256,1024]   tiled fp32 SGEMM
#define BM 128
#define BN 128
#define BK 16
__global__ void k_sgemm_cov(const float* __restrict__ A) {
    __shared__ __align__(16) float As[BK][BM];
    __shared__ __align__(16) float Bs[BK][BN];
    const float* B = g_Wfold_cov;
    int t = threadIdx.x;            // 256
    int bm = blockIdx.y * BM;
    int bn = blockIdx.x * BN;
    int trow = (t >> 4) << 3;       // 0..120
    int tcol = (t & 15) << 3;       // 0..120
    float acc[8][8];
#pragma unroll
    for (int i = 0; i < 8; i++)
#pragma unroll
        for (int j = 0; j < 8; j++) acc[i][j] = 0.f;

    for (int k0 = 0; k0 < 256; k0 += BK) {
        // load A tile: 128 rows x 16 k = 512 float4
#pragma unroll
        for (int i = 0; i < 2; i++) {
            int f = i * 256 + t;
            int row = f >> 2, kq = (f & 3) << 2;
            float4 v = make_float4(0, 0, 0, 0);
            int grow = bm + row;
            if (grow < NN) v = *(const float4*)(A + (size_t)grow * 256 + k0 + kq);
            As[kq + 0][row] = v.x; As[kq + 1][row] = v.y;
            As[kq + 2][row] = v.z; As[kq + 3][row] = v.w;
        }
        // load B tile: 16 rows x 128 cols = 512 float4
#pragma unroll
        for (int i = 0; i < 2; i++) {
            int f = i * 256 + t;
            int kr = f >> 5, cq = (f & 31) << 2;
            *(float4*)&Bs[kr][cq] = *(const float4*)(B + (size_t)(k0 + kr) * 1024 + bn + cq);
        }
        __syncthreads();
#pragma unroll
        for (int k = 0; k < BK; k++) {
            float a[8], b[8];
            *(float4*)&a[0] = *(const float4*)&As[k][trow];
            *(float4*)&a[4] = *(const float4*)&As[k][trow + 4];
            *(float4*)&b[0] = *(const float4*)&Bs[k][tcol];
            *(float4*)&b[4] = *(const float4*)&Bs[k][tcol + 4];
#pragma unroll
            for (int i = 0; i < 8; i++)
#pragma unroll
                for (int j = 0; j < 8; j++) acc[i][j] += a[i] * b[j];
        }
        __syncthreads();
    }
#pragma unroll
    for (int i = 0; i < 8; i++) {
        int grow = bm + trow + i;
        if (grow < NN) {
            float* cp = g_xh_cov + (size_t)grow * 1024 + bn + tcol;
            *(float4*)cp       = make_float4(acc[i][0], acc[i][1], acc[i][2], acc[i][3]);
            *(float4*)(cp + 4) = make_float4(acc[i][4], acc[i][5], acc[i][6], acc[i][7]);
        }
    }
}

// xh_mean = mean[50000,16] @ Wfold_mean[16,64]   (16 rows per block)
__global__ void k_gemm_mean(const float* __restrict__ X) {
    __shared__ float xs[16][16];
    __shared__ float ws[16][64];
    int t = threadIdx.x;
    int row0 = blockIdx.x * 16;
    xs[t >> 4][t & 15] = X[(size_t)row0 * 16 + t];
    for (int i = t; i < 1024; i += 256) ws[i >> 6][i & 63] = g_Wfold_mean[i];
    __syncthreads();
    int r = t >> 4, cg = (t & 15) << 2;
    float4 acc = make_float4(0, 0, 0, 0);
#pragma unroll
    for (int k = 0; k < 16; k++) {
        float a = xs[r][k];
        acc.x += a * ws[k][cg + 0];
        acc.y += a * ws[k][cg + 1];
        acc.z += a * ws[k][cg + 2];
        acc.w += a * ws[k][cg + 3];
    }
    *(float4*)(g_xh_mean + (size_t)(row0 + r) * 64 + cg) = acc;
}

// ---------------- aggregation (softmax + weighted gather) ----------------
__global__ void k_agg_cov(float* __restrict__ out) {
    __shared__ float4 cfs[256];
    __shared__ int    srcs[256];
    __shared__ float4 s_mx, s_inv;
    int dst = blockIdx.x;
    int t = threadIdx.x;
    int beg = g_offsets[dst];
    int deg = g_offsets[dst + 1] - beg;
    if (t < 32) {
        float4 mx = make_float4(-1e30f, -1e30f, -1e30f, -1e30f);
        for (int j = t; j < deg; j += 32) {
            float4 a = g_alpha_cov[beg + j];
            mx.x = fmaxf(mx.x, a.x); mx.y = fmaxf(mx.y, a.y);
            mx.z = fmaxf(mx.z, a.z); mx.w = fmaxf(mx.w, a.w);
        }
        wred_max4(mx);
        float4 sm = make_float4(0, 0, 0, 0);
        for (int j = t; j < deg; j += 32) {
            float4 a = g_alpha_cov[beg + j];
            sm.x += __expf(a.x - mx.x); sm.y += __expf(a.y - mx.y);
            sm.z += __expf(a.z - mx.z); sm.w += __expf(a.w - mx.w);
        }
        wred_sum4(sm);
        if (t == 0) {
            s_mx = mx;
            s_inv = make_float4(1.f / (sm.x + 1e-16f), 1.f / (sm.y + 1e-16f),
                                1.f / (sm.z + 1e-16f), 1.f / (sm.w + 1e-16f));
        }
    }
    __syncthreads();
    float acc = 0.f;
    for (int c0 = 0; c0 < deg; c0 += 256) {
        int cnt = min(256, deg - c0);
        if (t < cnt) {
            float4 a = g_alpha_cov[beg + c0 + t];
            cfs[t] = make_float4(__expf(a.x - s_mx.x) * s_inv.x,
                                 __expf(a.y - s_mx.y) * s_inv.y,
                                 __expf(a.z - s_mx.z) * s_inv.z,
                                 __expf(a.w - s_mx.w) * s_inv.w);
            srcs[t] = g_csr_src[beg + c0 + t];
        }
        __syncthreads();
        for (int j = 0; j < cnt; j++) {
            float4 cf = cfs[j];
            const float* xr = g_xh_cov + (size_t)srcs[j] * 1024 + t;
            acc += cf.x * __ldg(xr) + cf.y * __ldg(xr + 256)
                 + cf.z * __ldg(xr + 512) + cf.w * __ldg(xr + 768);
        }
        __syncthreads();
    }
    out[(size_t)dst * 256 + t] = acc * 0.25f + g_bias_cov_out[t];
}

__global__ void k_agg_mean(float* __restrict__ out) {
    int warp = threadIdx.x >> 5, lane = threadIdx.x & 31;
    int dst = blockIdx.x * 8 + warp;
    if (dst >= NN) return;
    int beg = g_offsets[dst];
    int deg = g_offsets[dst + 1] - beg;
    float4 mx = make_float4(-1e30f, -1e30f, -1e30f, -1e30f);
    for (int j = lane; j < deg; j += 32) {
        float4 a = g_alpha_mean[beg + j];
        mx.x = fmaxf(mx.x, a.x); mx.y = fmaxf(mx.y, a.y);
        mx.z = fmaxf(mx.z, a.z); mx.w = fmaxf(mx.w, a.w);
    }
    wred_max4(mx);
    float4 sm = make_float4(0, 0, 0, 0);
    for (int j = lane; j < deg; j += 32) {
        float4 a = g_alpha_mean[beg + j];
        sm.x += __expf(a.x - mx.x); sm.y += __expf(a.y - mx.y);
        sm.z += __expf(a.z - mx.z); sm.w += __expf(a.w - mx.w);
    }
    wred_sum4(sm);
    float4 inv = make_float4(1.f / (sm.x + 1e-16f), 1.f / (sm.y + 1e-16f),
                             1.f / (sm.z + 1e-16f), 1.f / (sm.w + 1e-16f));
    int c = lane & 15, hi = lane >> 4;
    float acc = 0.f;
    for (int j = 0; j < deg; j++) {
        float4 a = g_alpha_mean[beg + j];
        int s = g_csr_src[beg + j];
        const float* xr = g_xh_mean + (size_t)s * 64 + c;
        if (hi == 0)
            acc += __expf(a.x - mx.x) * inv.x * __ldg(xr)
                 + __expf(a.y - mx.y) * inv.y * __ldg(xr + 16);
        else
            acc += __expf(a.z - mx.z) * inv.z * __ldg(xr + 32)
                 + __expf(a.w - mx.w) * inv.w * __ldg(xr + 48);
    }
    acc += __shfl_xor_sync(0xffffffffu, acc, 16);
    if (hi == 0) out[(size_t)dst * 16 + c] = acc * 0.25f + g_bias_mean_out[c];
}

// ---------------- launch ----------------
extern "C" void kernel_launch(void* const* d_in, const int* in_sizes, int n_in,
                              void* d_out, int out_size) {
    const float* mean        = (const float*)d_in[0];
    const float* cov         = (const float*)d_in[1];
    const int*   edge_index  = (const int*)  d_in[2];
    const float* W_mean      = (const float*)d_in[3];
    const float* att_src_m   = (const float*)d_in[4];
    const float* att_dst_m   = (const float*)d_in[5];
    const float* bias_mean   = (const float*)d_in[6];
    const float* W_cov       = (const float*)d_in[7];
    const float* att_src_c   = (const float*)d_in[8];
    const float* att_dst_c   = (const float*)d_in[9];
    const float* bias_cov    = (const float*)d_in[10];
    const float* fm_W1       = (const float*)d_in[11];
    const float* fm_b1       = (const float*)d_in[12];
    const float* fm_W2       = (const float*)d_in[13];
    const float* fm_b2       = (const float*)d_in[14];
    const float* fcv_W1      = (const float*)d_in[15];
    const float* fcv_b1      = (const float*)d_in[16];
    const float* fcv_W2      = (const float*)d_in[17];
    const float* fcv_b2      = (const float*)d_in[18];
    float* outp = (float*)d_out;

    // precomputes (folding)
    k_prep_mean<<<1, 256>>>(fm_W1, fm_W2, fm_b1, fm_b2, bias_mean, W_mean, att_src_m, att_dst_m);
    k_Wc2<<<256, 256>>>(fcv_W1, fcv_W2);
    k_bias_cov<<<1, 256>>>(bias_cov, fcv_b1, fcv_W2, fcv_b2);
    k_Wfold_cov<<<1024, 256>>>(W_cov);
    k_att_cov<<<8, 256>>>(W_cov, att_src_c, att_dst_c);

    // per-node logits
    k_a<<<(NN + 7) / 8, 256>>>(mean, cov);

    // CSR build
    k_init_counts<<<(NN + 255) / 256, 256>>>();
    k_hist<<<(EE + 255) / 256, 256>>>(edge_index);
    k_scan<<<1, 1024>>>();
    k_scatter<<<(ETOT + 255) / 256, 256>>>(edge_index);

    // projections
    dim3 gemm_grid(1024 / BN, (NN + BM - 1) / BM);
    k_sgemm_cov<<<gemm_grid, 256>>>(cov);
    k_gemm_mean<<<NN / 16, 256>>>(mean);

    // softmax-weighted aggregation -> outputs (mean first, then cov, row-major)
    k_agg_cov<<<NN, 256>>>(outp + (size_t)NN * 16);
    k_agg_mean<<<(NN + 7) / 8, 256>>>(outp);
}

// round 3
// speedup vs baseline: 1.9979x; 1.9979x over previous
#include <cuda_runtime.h>
#include <cstdint>

#define NN 50000
#define EE 800000
#define ETOT (EE + NN)

// ---------------- scratch ----------------
__device__ float  g_z[(size_t)NN * 1024];        // [N, H=4 x 256] aggregated raw cov per head (tf32-rounded)
__device__ float  g_xh_mean[(size_t)NN * 64];    // [N, 4, 16]
__device__ float4 g_asrc_cov[NN], g_adst_cov[NN];
__device__ float4 g_asrc_mean[NN], g_adst_mean[NN];
__device__ float  g_Wc2[256 * 256];              // fcv_W1 @ fcv_W2
__device__ float  g_BT[256 * 1024];              // [c][h*256+j] = 0.25*Wfold[j][h*256+c] (tf32-rounded)
__device__ float  g_Wfold_mean[16 * 64];
__device__ float4 g_wsrc_cov[256], g_wdst_cov[256];
__device__ float4 g_wsrc_mean[16], g_wdst_mean[16];
__device__ float  g_bias_cov_out[256];
__device__ float  g_bias_mean_out[16];
__device__ int    g_counts[NN];
__device__ int    g_offsets[NN + 1];
__device__ int    g_cursor[NN];
__device__ int    g_csr_src[ETOT];
__device__ float4 g_alpha_cov[ETOT];
__device__ float4 g_alpha_mean[ETOT];

__device__ __forceinline__ float lrelu(float x) { return x > 0.f ? x : 0.2f * x; }

__device__ __forceinline__ float to_tf32(float x) {
    float r;
    asm("cvt.rna.tf32.f32 %0, %1;" : "=f"(r) : "f"(x));
    return r;
}

__device__ __forceinline__ void wred_max4(float4& v) {
#pragma unroll
    for (int o = 16; o; o >>= 1) {
        v.x = fmaxf(v.x, __shfl_xor_sync(0xffffffffu, v.x, o));
        v.y = fmaxf(v.y, __shfl_xor_sync(0xffffffffu, v.y, o));
        v.z = fmaxf(v.z, __shfl_xor_sync(0xffffffffu, v.z, o));
        v.w = fmaxf(v.w, __shfl_xor_sync(0xffffffffu, v.w, o));
    }
}
__device__ __forceinline__ void wred_sum4(float4& v) {
#pragma unroll
    for (int o = 16; o; o >>= 1) {
        v.x += __shfl_xor_sync(0xffffffffu, v.x, o);
        v.y += __shfl_xor_sync(0xffffffffu, v.y, o);
        v.z += __shfl_xor_sync(0xffffffffu, v.z, o);
        v.w += __shfl_xor_sync(0xffffffffu, v.w, o);
    }
}

// ---------------- cp.async helpers (sm_80+, no 'a' features) ----------------
__device__ __forceinline__ uint32_t smem_u32(const void* p) {
    uint32_t a;
    asm("{ .reg .u64 tmp; cvta.to.shared.u64 tmp, %1; cvt.u32.u64 %0, tmp; }" : "=r"(a) : "l"(p));
    return a;
}
__device__ __forceinline__ void cp16(uint32_t dst, const void* src, int sz) {
    asm volatile("cp.async.cg.shared.global [%0], [%1], 16, %2;" :: "r"(dst), "l"(src), "r"(sz));
}
#define CP_COMMIT() asm volatile("cp.async.commit_group;" ::: "memory")

#define MMA_TF32(d, a, b) \
    asm volatile("mma.sync.aligned.m16n8k8.row.col.f32.tf32.tf32.f32 " \
        "{%0,%1,%2,%3}, {%4,%5,%6,%7}, {%8,%9}, {%0,%1,%2,%3};" \
        : "+f"((d)[0]), "+f"((d)[1]), "+f"((d)[2]), "+f"((d)[3]) \
        : "r"((a)[0]), "r"((a)[1]), "r"((a)[2]), "r"((a)[3]), "r"((b)[0]), "r"((b)[1]))

// ---------------- tiny precompute kernels ----------------

__global__ void k_prep_mean(const float* __restrict__ fmW1, const float* __restrict__ fmW2,
                            const float* __restrict__ fmb1, const float* __restrict__ fmb2,
                            const float* __restrict__ bias_mean, const float* __restrict__ W_mean,
                            const float* __restrict__ att_src, const float* __restrict__ att_dst) {
    __shared__ float Wm2s[16][16];
    int t = threadIdx.x;
    {
        int r = t >> 4, c = t & 15;
        float s = 0.f;
        for (int k = 0; k < 16; k++) s += fmW1[r * 16 + k] * fmW2[k * 16 + c];
        Wm2s[r][c] = s;
    }
    if (t < 128) {
        int sd = t >> 6, rem = t & 63, r = rem >> 2, h = rem & 3;
        const float* att = sd ? att_dst : att_src;
        float s = 0.f;
        for (int j = 0; j < 16; j++) s += W_mean[r * 64 + h * 16 + j] * att[h * 16 + j];
        float* dstp = sd ? (float*)g_wdst_mean : (float*)g_wsrc_mean;
        dstp[r * 4 + h] = s;
    }
    __syncthreads();
    if (t < 16) {
        float b = fmb2[t];
        for (int k = 0; k < 16; k++)
            b += bias_mean[k] * Wm2s[k][t] + fmb1[k] * fmW2[k * 16 + t];
        g_bias_mean_out[t] = b;
    }
    for (int o = t; o < 1024; o += 256) {
        int r = o >> 6, hc = o & 63, h = hc >> 4, c = hc & 15;
        float s = 0.f;
        for (int j = 0; j < 16; j++) s += W_mean[r * 64 + h * 16 + j] * Wm2s[j][c];
        g_Wfold_mean[o] = s;
    }
}

__global__ void k_Wc2(const float* __restrict__ W1, const float* __restrict__ W2) {
    int r = blockIdx.x, c = threadIdx.x;
    float s = 0.f;
    for (int k = 0; k < 256; k++) s += W1[r * 256 + k] * W2[k * 256 + c];
    g_Wc2[r * 256 + c] = s;
}

__global__ void k_bias_cov(const float* __restrict__ bias_cov, const float* __restrict__ fb1,
                           const float* __restrict__ fW2, const float* __restrict__ fb2) {
    int c = threadIdx.x;
    float b = fb2[c];
    for (int k = 0; k < 256; k++)
        b += bias_cov[k] * g_Wc2[k * 256 + c] + fb1[k] * fW2[k * 256 + c];
    g_bias_cov_out[c] = b;
}

// g_BT[c][seg*256+r] = tf32(0.25 * sum_j W_cov[r][seg*256+j] * Wc2[j][c])
__global__ void k_Wfold_cov(const float* __restrict__ W_cov) {
    __shared__ float wc2s[32][256];
    __shared__ float wr[8][256];
    int seg = blockIdx.x & 3, r0 = (blockIdx.x >> 2) * 8;
    int t = threadIdx.x;
    float acc[8];
#pragma unroll
    for (int i = 0; i < 8; i++) acc[i] = 0.f;
#pragma unroll
    for (int i = 0; i < 8; i++)
        wr[i][t] = W_cov[(size_t)(r0 + i) * 1024 + seg * 256 + t];
    __syncthreads();
    for (int j0 = 0; j0 < 256; j0 += 32) {
        for (int i = 0; i < 32; i++)
            wc2s[i][t] = g_Wc2[(size_t)(j0 + i) * 256 + t];
        __syncthreads();
#pragma unroll
        for (int jj = 0; jj < 32; jj++) {
            float b = wc2s[jj][t];
#pragma unroll
            for (int i = 0; i < 8; i++) acc[i] += wr[i][j0 + jj] * b;
        }
        __syncthreads();
    }
#pragma unroll
    for (int i = 0; i < 8; i++)
        g_BT[(size_t)t * 1024 + seg * 256 + r0 + i] = to_tf32(0.25f * acc[i]);
}

__global__ void k_att_cov(const float* __restrict__ W_cov, const float* __restrict__ att_src,
                          const float* __restrict__ att_dst) {
    int o = blockIdx.x * 256 + threadIdx.x;
    int sd = o >> 10, rem = o & 1023, r = rem >> 2, h = rem & 3;
    const float* att = sd ? att_dst : att_src;
    const float* wrow = W_cov + (size_t)r * 1024 + h * 256;
    float s = 0.f;
    for (int j = 0; j < 256; j++) s += wrow[j] * att[h * 256 + j];
    float* dstp = sd ? (float*)g_wdst_cov : (float*)g_wsrc_cov;
    dstp[r * 4 + h] = s;
}

// per-node attention logits, warp per node
__global__ void k_a(const float* __restrict__ mean, const float* __restrict__ cov) {
    int warp = threadIdx.x >> 5, lane = threadIdx.x & 31;
    int n = blockIdx.x * 8 + warp;
    if (n >= NN) return;
    const float* x = cov + (size_t)n * 256;
    float4 as = make_float4(0, 0, 0, 0), ad = make_float4(0, 0, 0, 0);
    for (int r = lane; r < 256; r += 32) {
        float xv = __ldg(x + r);
        float4 ws = g_wsrc_cov[r], wd = g_wdst_cov[r];
        as.x += xv * ws.x; as.y += xv * ws.y; as.z += xv * ws.z; as.w += xv * ws.w;
        ad.x += xv * wd.x; ad.y += xv * wd.y; ad.z += xv * wd.z; ad.w += xv * wd.w;
    }
    wred_sum4(as); wred_sum4(ad);
    float4 ms = make_float4(0, 0, 0, 0), md = make_float4(0, 0, 0, 0);
    if (lane < 16) {
        float xv = __ldg(mean + (size_t)n * 16 + lane);
        float4 ws = g_wsrc_mean[lane], wd = g_wdst_mean[lane];
        ms = make_float4(xv * ws.x, xv * ws.y, xv * ws.z, xv * ws.w);
        md = make_float4(xv * wd.x, xv * wd.y, xv * wd.z, xv * wd.w);
    }
    wred_sum4(ms); wred_sum4(md);
    if (lane == 0) {
        g_asrc_cov[n] = as; g_adst_cov[n] = ad;
        g_asrc_mean[n] = ms; g_adst_mean[n] = md;
    }
}

// ---------------- CSR build ----------------
__global__ void k_init_counts() {
    int i = blockIdx.x * 256 + threadIdx.x;
    if (i < NN) g_counts[i] = 1;
}
__global__ void k_hist(const int* __restrict__ ei) {
    int e = blockIdx.x * 256 + threadIdx.x;
    if (e < EE) atomicAdd(&g_counts[ei[EE + e]], 1);
}
__global__ void k_scan() {
    __shared__ int ssum[1024];
    int t = threadIdx.x;
    const int PER = (NN + 1023) / 1024;
    int base = t * PER;
    int local = 0;
    for (int i = 0; i < PER; i++) { int idx = base + i; if (idx < NN) local += g_counts[idx]; }
    ssum[t] = local;
    __syncthreads();
    for (int off = 1; off < 1024; off <<= 1) {
        int v = (t >= off) ? ssum[t - off] : 0;
        __syncthreads();
        ssum[t] += v;
        __syncthreads();
    }
    int prefix = (t == 0) ? 0 : ssum[t - 1];
    for (int i = 0; i < PER; i++) {
        int idx = base + i;
        if (idx < NN) {
            g_offsets[idx] = prefix;
            g_cursor[idx] = prefix;
            prefix += g_counts[idx];
        }
    }
    if (t == 1023) g_offsets[NN] = ssum[1023];
}
__global__ void k_scatter(const int* __restrict__ ei) {
    int e = blockIdx.x * 256 + threadIdx.x;
    if (e >= ETOT) return;
    int s, d;
    if (e < EE) { s = ei[e]; d = ei[EE + e]; }
    else        { s = e - EE; d = s; }
    int pos = atomicAdd(&g_cursor[d], 1);
    g_csr_src[pos] = s;
    float4 a = g_asrc_cov[s], b = g_adst_cov[d];
    g_alpha_cov[pos] = make_float4(lrelu(a.x + b.x), lrelu(a.y + b.y),
                                   lrelu(a.z + b.z), lrelu(a.w + b.w));
    a = g_asrc_mean[s]; b = g_adst_mean[d];
    g_alpha_mean[pos] = make_float4(lrelu(a.x + b.x), lrelu(a.y + b.y),
                                    lrelu(a.z + b.z), lrelu(a.w + b.w));
}

// ---------------- aggregation of RAW cov into z ----------------
__global__ void k_agg_cov_z(const float* __restrict__ cov) {
    __shared__ float4 cfs[256];
    __shared__ int    srcs[256];
    __shared__ float4 s_mx, s_inv;
    int dst = blockIdx.x;
    int t = threadIdx.x;
    int beg = g_offsets[dst];
    int deg = g_offsets[dst + 1] - beg;
    if (t < 32) {
        float4 mx = make_float4(-1e30f, -1e30f, -1e30f, -1e30f);
        for (int j = t; j < deg; j += 32) {
            float4 a = g_alpha_cov[beg + j];
            mx.x = fmaxf(mx.x, a.x); mx.y = fmaxf(mx.y, a.y);
            mx.z = fmaxf(mx.z, a.z); mx.w = fmaxf(mx.w, a.w);
        }
        wred_max4(mx);
        float4 sm = make_float4(0, 0, 0, 0);
        for (int j = t; j < deg; j += 32) {
            float4 a = g_alpha_cov[beg + j];
            sm.x += __expf(a.x - mx.x); sm.y += __expf(a.y - mx.y);
            sm.z += __expf(a.z - mx.z); sm.w += __expf(a.w - mx.w);
        }
        wred_sum4(sm);
        if (t == 0) {
            s_mx = mx;
            s_inv = make_float4(1.f / (sm.x + 1e-16f), 1.f / (sm.y + 1e-16f),
                                1.f / (sm.z + 1e-16f), 1.f / (sm.w + 1e-16f));
        }
    }
    __syncthreads();
    float a0 = 0.f, a1 = 0.f, a2 = 0.f, a3 = 0.f;
    for (int c0 = 0; c0 < deg; c0 += 256) {
        int cnt = min(256, deg - c0);
        if (t < cnt) {
            float4 a = g_alpha_cov[beg + c0 + t];
            cfs[t] = make_float4(__expf(a.x - s_mx.x) * s_inv.x,
                                 __expf(a.y - s_mx.y) * s_inv.y,
                                 __expf(a.z - s_mx.z) * s_inv.z,
                                 __expf(a.w - s_mx.w) * s_inv.w);
            srcs[t] = g_csr_src[beg + c0 + t];
        }
        __syncthreads();
        for (int j = 0; j < cnt; j++) {
            float4 cf = cfs[j];
            float v = __ldg(cov + (size_t)srcs[j] * 256 + t);
            a0 += cf.x * v; a1 += cf.y * v; a2 += cf.z * v; a3 += cf.w * v;
        }
        __syncthreads();
    }
    float* zp = g_z + (size_t)dst * 1024 + t;
    zp[0]   = to_tf32(a0);
    zp[256] = to_tf32(a1);
    zp[512] = to_tf32(a2);
    zp[768] = to_tf32(a3);
}

// ---------------- tf32 mma.sync GEMM: out = z[50000,1024] @ BT^T + bias ----------------
// BM=128, BN=128, BK=32; 8 warps in 2x4; warp tile 64x32; m16n8k8.
#define SG_STRIDE 36                      // 32 + 4 pad, conflict-free fragments
#define SG_BUFSZ  (128 * SG_STRIDE)      // floats per (A or B) buffer
#define SG_SMEM_FLOATS (SG_BUFSZ * 4)    // A0,A1,B0,B1
__global__ void __launch_bounds__(256) k_mma_cov(float* __restrict__ out) {
    extern __shared__ float smf[];
    uint32_t sbase = smem_u32(smf);
    int t = threadIdx.x, wid = t >> 5, lane = t & 31;
    int tq = lane >> 2, tr = lane & 3;
    int bm = blockIdx.y * 128;
    int bn = blockIdx.x * 128;
    int wm = (wid >> 2) * 64;
    int wn = (wid & 3) * 32;

    float acc[4][4][4];
#pragma unroll
    for (int mi = 0; mi < 4; mi++)
#pragma unroll
        for (int ni = 0; ni < 4; ni++)
#pragma unroll
            for (int q = 0; q < 4; q++) acc[mi][ni][q] = 0.f;

    int row = t >> 3, q8 = t & 7;      // each thread owns (row, q8) chunk per 2048-float4 stage? no: 256 thr x (4 A + 4 B)
    // stage lambda: c = k-chunk index (32 floats)
    auto stage = [&](int c, int buf) {
        int kc = c * 32;
        uint32_t aoff = sbase + (uint32_t)(buf * SG_BUFSZ) * 4;
        uint32_t boff = sbase + (uint32_t)((2 + buf) * SG_BUFSZ) * 4;
#pragma unroll
        for (int i = 0; i < 4; i++) {
            int f = i * 256 + t;
            int r = f >> 3, q = f & 7;
            int gr = bm + r;
            const float* src = g_z + (size_t)(gr < NN ? gr : NN - 1) * 1024 + kc + q * 4;
            cp16(aoff + (uint32_t)(r * SG_STRIDE + q * 4) * 4, src, gr < NN ? 16 : 0);
        }
#pragma unroll
        for (int i = 0; i < 4; i++) {
            int f = i * 256 + t;
            int r = f >> 3, q = f & 7;
            const float* src = g_BT + (size_t)(bn + r) * 1024 + kc + q * 4;
            cp16(boff + (uint32_t)(r * SG_STRIDE + q * 4) * 4, src, 16);
        }
        CP_COMMIT();
    };

    stage(0, 0);
    for (int c = 0; c < 32; c++) {
        int buf = c & 1;
        if (c < 31) {
            stage(c + 1, (c + 1) & 1);
            asm volatile("cp.async.wait_group 1;" ::: "memory");
        } else {
            asm volatile("cp.async.wait_group 0;" ::: "memory");
        }
        __syncthreads();
        const float* As = smf + buf * SG_BUFSZ;
        const float* Bs = smf + (2 + buf) * SG_BUFSZ;
#pragma unroll
        for (int kk = 0; kk < 4; kk++) {
            int k8 = kk * 8;
            uint32_t af[4][4], bf[4][2];
#pragma unroll
            for (int mi = 0; mi < 4; mi++) {
                const float* ap = As + (wm + mi * 16 + tq) * SG_STRIDE + k8 + tr;
                af[mi][0] = __float_as_uint(ap[0]);
                af[mi][1] = __float_as_uint(ap[8 * SG_STRIDE]);
                af[mi][2] = __float_as_uint(ap[4]);
                af[mi][3] = __float_as_uint(ap[8 * SG_STRIDE + 4]);
            }
#pragma unroll
            for (int ni = 0; ni < 4; ni++) {
                const float* bp = Bs + (wn + ni * 8 + tq) * SG_STRIDE + k8 + tr;
                bf[ni][0] = __float_as_uint(bp[0]);
                bf[ni][1] = __float_as_uint(bp[4]);
            }
#pragma unroll
            for (int mi = 0; mi < 4; mi++)
#pragma unroll
                for (int ni = 0; ni < 4; ni++)
                    MMA_TF32(acc[mi][ni], af[mi], bf[ni]);
        }
        __syncthreads();
    }

    // epilogue: add bias, store
#pragma unroll
    for (int mi = 0; mi < 4; mi++) {
#pragma unroll
        for (int ni = 0; ni < 4; ni++) {
            int cc = bn + wn + ni * 8 + 2 * tr;
            float b0 = g_bias_cov_out[cc], b1 = g_bias_cov_out[cc + 1];
            int r0 = bm + wm + mi * 16 + tq;
            if (r0 < NN) {
                float2 v = make_float2(acc[mi][ni][0] + b0, acc[mi][ni][1] + b1);
                *(float2*)(out + (size_t)r0 * 256 + cc) = v;
            }
            int r1 = r0 + 8;
            if (r1 < NN) {
                float2 v = make_float2(acc[mi][ni][2] + b0, acc[mi][ni][3] + b1);
                *(float2*)(out + (size_t)r1 * 256 + cc) = v;
            }
        }
    }
}

// ---------------- mean path ----------------
__global__ void k_gemm_mean(const float* __restrict__ X) {
    __shared__ float xs[16][16];
    __shared__ float ws[16][64];
    int t = threadIdx.x;
    int row0 = blockIdx.x * 16;
    xs[t >> 4][t & 15] = X[(size_t)row0 * 16 + t];
    for (int i = t; i < 1024; i += 256) ws[i >> 6][i & 63] = g_Wfold_mean[i];
    __syncthreads();
    int r = t >> 4, cg = (t & 15) << 2;
    float4 acc = make_float4(0, 0, 0, 0);
#pragma unroll
    for (int k = 0; k < 16; k++) {
        float a = xs[r][k];
        acc.x += a * ws[k][cg + 0];
        acc.y += a * ws[k][cg + 1];
        acc.z += a * ws[k][cg + 2];
        acc.w += a * ws[k][cg + 3];
    }
    *(float4*)(g_xh_mean + (size_t)(row0 + r) * 64 + cg) = acc;
}

__global__ void k_agg_mean(float* __restrict__ out) {
    int warp = threadIdx.x >> 5, lane = threadIdx.x & 31;
    int dst = blockIdx.x * 8 + warp;
    if (dst >= NN) return;
    int beg = g_offsets[dst];
    int deg = g_offsets[dst + 1] - beg;
    float4 mx = make_float4(-1e30f, -1e30f, -1e30f, -1e30f);
    for (int j = lane; j < deg; j += 32) {
        float4 a = g_alpha_mean[beg + j];
        mx.x = fmaxf(mx.x, a.x); mx.y = fmaxf(mx.y, a.y);
        mx.z = fmaxf(mx.z, a.z); mx.w = fmaxf(mx.w, a.w);
    }
    wred_max4(mx);
    float4 sm = make_float4(0, 0, 0, 0);
    for (int j = lane; j < deg; j += 32) {
        float4 a = g_alpha_mean[beg + j];
        sm.x += __expf(a.x - mx.x); sm.y += __expf(a.y - mx.y);
        sm.z += __expf(a.z - mx.z); sm.w += __expf(a.w - mx.w);
    }
    wred_sum4(sm);
    float4 inv = make_float4(1.f / (sm.x + 1e-16f), 1.f / (sm.y + 1e-16f),
                             1.f / (sm.z + 1e-16f), 1.f / (sm.w + 1e-16f));
    int c = lane & 15, hi = lane >> 4;
    float acc = 0.f;
    for (int j = 0; j < deg; j++) {
        float4 a = g_alpha_mean[beg + j];
        int s = g_csr_src[beg + j];
        const float* xr = g_xh_mean + (size_t)s * 64 + c;
        if (hi == 0)
            acc += __expf(a.x - mx.x) * inv.x * __ldg(xr)
                 + __expf(a.y - mx.y) * inv.y * __ldg(xr + 16);
        else
            acc += __expf(a.z - mx.z) * inv.z * __ldg(xr + 32)
                 + __expf(a.w - mx.w) * inv.w * __ldg(xr + 48);
    }
    acc += __shfl_xor_sync(0xffffffffu, acc, 16);
    if (hi == 0) out[(size_t)dst * 16 + c] = acc * 0.25f + g_bias_mean_out[c];
}

// ---------------- launch ----------------
extern "C" void kernel_launch(void* const* d_in, const int* in_sizes, int n_in,
                              void* d_out, int out_size) {
    const float* mean        = (const float*)d_in[0];
    const float* cov         = (const float*)d_in[1];
    const int*   edge_index  = (const int*)  d_in[2];
    const float* W_mean      = (const float*)d_in[3];
    const float* att_src_m   = (const float*)d_in[4];
    const float* att_dst_m   = (const float*)d_in[5];
    const float* bias_mean   = (const float*)d_in[6];
    const float* W_cov       = (const float*)d_in[7];
    const float* att_src_c   = (const float*)d_in[8];
    const float* att_dst_c   = (const float*)d_in[9];
    const float* bias_cov    = (const float*)d_in[10];
    const float* fm_W1       = (const float*)d_in[11];
    const float* fm_b1       = (const float*)d_in[12];
    const float* fm_W2       = (const float*)d_in[13];
    const float* fm_b2       = (const float*)d_in[14];
    const float* fcv_W1      = (const float*)d_in[15];
    const float* fcv_b1      = (const float*)d_in[16];
    const float* fcv_W2      = (const float*)d_in[17];
    const float* fcv_b2      = (const float*)d_in[18];
    float* outp = (float*)d_out;

    static int smem_set = 0;
    if (!smem_set) {
        cudaFuncSetAttribute(k_mma_cov, cudaFuncAttributeMaxDynamicSharedMemorySize,
                             SG_SMEM_FLOATS * 4);
        smem_set = 1;
    }

    // folding precomputes
    k_prep_mean<<<1, 256>>>(fm_W1, fm_W2, fm_b1, fm_b2, bias_mean, W_mean, att_src_m, att_dst_m);
    k_Wc2<<<256, 256>>>(fcv_W1, fcv_W2);
    k_bias_cov<<<1, 256>>>(bias_cov, fcv_b1, fcv_W2, fcv_b2);
    k_Wfold_cov<<<128, 256>>>(W_cov);
    k_att_cov<<<8, 256>>>(W_cov, att_src_c, att_dst_c);

    // per-node logits
    k_a<<<(NN + 7) / 8, 256>>>(mean, cov);

    // CSR build
    k_init_counts<<<(NN + 255) / 256, 256>>>();
    k_hist<<<(EE + 255) / 256, 256>>>(edge_index);
    k_scan<<<1, 1024>>>();
    k_scatter<<<(ETOT + 255) / 256, 256>>>(edge_index);

    // aggregate raw cov -> z, then tensor-core projection (tf32 mma.sync)
    k_agg_cov_z<<<NN, 256>>>(cov);
    dim3 gg(2, (NN + 127) / 128);
    k_mma_cov<<<gg, 256, SG_SMEM_FLOATS * 4>>>(outp + (size_t)NN * 16);

    // mean path
    k_gemm_mean<<<NN / 16, 256>>>(mean);
    k_agg_mean<<<(NN + 7) / 8, 256>>>(outp);
}